// round 17
// baseline (speedup 1.0000x reference)
#include <cuda_runtime.h>
#include <cuda_fp16.h>
#include <math_constants.h>
#include <cstdint>

#define B_ 8
#define C_ 128
#define N_ 2304
#define BM 64
#define BN 64
#define NTILE 18
#define LOG2E 1.4426950408889634f

// ---------------- attention smem strides (halfs) ----------------
#define SQh 136
#define SKh 136
#define SVh 72
#define OFF_Q 0
#define OFF_K (BM*SQh)                    // 8704
#define OFF_V (OFF_K + 2*BN*SKh)          // 26112
#define SMEM_HALFS (OFF_V + 3*C_*SVh)     // 53760 halfs = 107520 B

// epilogue staging stride (floats): even (float2-aligned), ≡4 mod 32
#define SEP 132

// ---------------- qkv smem strides (halfs) ----------------
#define SX 136
#define SW 136
#define ST 136
#define QOFF_X  0
#define QOFF_W0 (C_*SX)                   // 17408
#define QOFF_T  (QOFF_W0 + 3*C_*SW)       // 69632
#define QKV_SMEM_HALFS (QOFF_T + C_*ST)   // 87040 halfs = 174080 B

__device__ __half g_qh[B_*N_*C_];   // [b][n][c]  (q pre-scaled by log2e)
__device__ __half g_kh[B_*N_*C_];   // [b][n][c]
__device__ __half g_vh[B_*C_*N_];   // [b][c][n]
__device__ float  g_ypart[B_*NTILE*C_];

// ---------------------------------------------------------------------------
__device__ __forceinline__ void cpa16(uint32_t s, const void* g){
    asm volatile("cp.async.cg.shared.global [%0], [%1], 16;" :: "r"(s), "l"(g));
}
__device__ __forceinline__ void cp_commit(){ asm volatile("cp.async.commit_group;"); }
__device__ __forceinline__ void cp_wait1(){ asm volatile("cp.async.wait_group 1;"); }
__device__ __forceinline__ void cp_wait0(){ asm volatile("cp.async.wait_group 0;"); }

__device__ __forceinline__ void ldsm4(uint32_t& r0,uint32_t& r1,uint32_t& r2,uint32_t& r3,
                                      uint32_t a){
    asm volatile("ldmatrix.sync.aligned.m8n8.x4.shared.b16 {%0,%1,%2,%3}, [%4];"
        : "=r"(r0),"=r"(r1),"=r"(r2),"=r"(r3) : "r"(a));
}
__device__ __forceinline__ void ldsm4t(uint32_t& r0,uint32_t& r1,uint32_t& r2,uint32_t& r3,
                                       uint32_t a){
    asm volatile("ldmatrix.sync.aligned.m8n8.x4.trans.shared.b16 {%0,%1,%2,%3}, [%4];"
        : "=r"(r0),"=r"(r1),"=r"(r2),"=r"(r3) : "r"(a));
}
__device__ __forceinline__ void stsm4t(uint32_t a, uint32_t r0,uint32_t r1,uint32_t r2,uint32_t r3){
    asm volatile("stmatrix.sync.aligned.m8n8.x4.trans.shared.b16 [%0], {%1,%2,%3,%4};"
        :: "r"(a), "r"(r0), "r"(r1), "r"(r2), "r"(r3));
}
__device__ __forceinline__ void sts32(uint32_t a, uint32_t v){
    asm volatile("st.shared.b32 [%0], %1;" :: "r"(a), "r"(v));
}
__device__ __forceinline__ void mma16(float* d, uint32_t a0,uint32_t a1,uint32_t a2,uint32_t a3,
                                      uint32_t b0,uint32_t b1){
    asm volatile(
      "mma.sync.aligned.m16n8k16.row.col.f32.f16.f16.f32 "
      "{%0,%1,%2,%3}, {%4,%5,%6,%7}, {%8,%9}, {%0,%1,%2,%3};"
      : "+f"(d[0]), "+f"(d[1]), "+f"(d[2]), "+f"(d[3])
      : "r"(a0), "r"(a1), "r"(a2), "r"(a3), "r"(b0), "r"(b1));
}
__device__ __forceinline__ uint32_t h2u(__half2 h){ return *reinterpret_cast<uint32_t*>(&h); }
__device__ __forceinline__ float ex2f(float x){
    float y; asm("ex2.approx.f32 %0, %1;" : "=f"(y) : "f"(x)); return y;
}
__device__ __forceinline__ uint32_t ex2_h2(uint32_t u){
    uint32_t r; asm("ex2.approx.f16x2 %0, %1;" : "=r"(r) : "r"(u)); return r;
}

// S-phase: s = Q * K^T for one 64x64 tile (per-warp 16x64)
__device__ __forceinline__ void s_phase(float s[8][4], uint32_t aQ, uint32_t kB){
    #pragma unroll
    for (int nt = 0; nt < 8; nt++)
        #pragma unroll
        for (int r = 0; r < 4; r++) s[nt][r] = 0.f;
    #pragma unroll
    for (int kc = 0; kc < 8; kc++) {
        uint32_t a0,a1,a2,a3;
        ldsm4(a0,a1,a2,a3, aQ + 32u*kc);
        #pragma unroll
        for (int np = 0; np < 4; np++) {
            uint32_t b0,b1,b2,b3;
            ldsm4(b0,b1,b2,b3, kB + 2u*(np*16*SKh + kc*16));
            mma16(s[2*np],   a0,a1,a2,a3, b0,b1);
            mma16(s[2*np+1], a0,a1,a2,a3, b2,b3);
        }
    }
}

// ---------------------------------------------------------------------------
// QKV via fp16 tensor cores; x AND weights converted fp32->fp16 inline.
// grid (N/128, B), block 256 (8 warps). No prep kernel.
// ---------------------------------------------------------------------------
__global__ void __launch_bounds__(256, 1) qkv_mma_kernel(
    const float* __restrict__ x,
    const float* __restrict__ Wq,
    const float* __restrict__ bq,
    const float* __restrict__ Wk,
    const float* __restrict__ bk,
    const float* __restrict__ Wv,
    const float* __restrict__ bv)
{
    extern __shared__ __half smh[];
    uint32_t sb = (uint32_t)__cvta_generic_to_shared(smh);

    const int tid  = threadIdx.x;
    const int b    = blockIdx.y;
    const int n0   = blockIdx.x * 128;
    const int warp = tid >> 5, lane = tid & 31;
    const int quad = lane >> 2, qt = lane & 3;

    const float* xb = x + (size_t)b * C_ * N_;

    // ---- x tile [c][n]: fp32 load + convert + smem store ----
    #pragma unroll
    for (int c2 = 0; c2 < 8; c2++) {
        int ch = tid + c2*256;
        int c = ch >> 4, nb = ch & 15;
        const float* src = xb + (size_t)c*N_ + n0 + nb*8;
        float4 v0 = *(const float4*)src;
        float4 v1 = *(const float4*)(src + 4);
        uint4 hv;
        hv.x = h2u(__floats2half2_rn(v0.x, v0.y));
        hv.y = h2u(__floats2half2_rn(v0.z, v0.w));
        hv.z = h2u(__floats2half2_rn(v1.x, v1.y));
        hv.w = h2u(__floats2half2_rn(v1.z, v1.w));
        *(uint4*)&smh[QOFF_X + c*SX + nb*8] = hv;
    }

    // ---- W0/W1/W2: fp32 load (L2-hot) + convert + smem store ----
    #pragma unroll
    for (int wi = 0; wi < 3; wi++) {
        const float* Wm = (wi == 0) ? Wq : (wi == 1) ? Wk : Wv;
        #pragma unroll
        for (int c2 = 0; c2 < 8; c2++) {
            int ch = tid + c2*256;
            int o = ch >> 4, cb = ch & 15;
            const float* src = Wm + o*C_ + cb*8;
            float4 v0 = *(const float4*)src;
            float4 v1 = *(const float4*)(src + 4);
            uint4 hv;
            hv.x = h2u(__floats2half2_rn(v0.x, v0.y));
            hv.y = h2u(__floats2half2_rn(v0.z, v0.w));
            hv.z = h2u(__floats2half2_rn(v1.x, v1.y));
            hv.w = h2u(__floats2half2_rn(v1.z, v1.w));
            *(uint4*)&smh[QOFF_W0 + wi*C_*SW + o*SW + cb*8] = hv;
        }
    }
    __syncthreads();

    // ---- SE partial: per-channel sum of this x tile ----
    if (tid < C_) {
        const uint4* row = (const uint4*)&smh[QOFF_X + tid*SX];
        float s = 0.f;
        #pragma unroll
        for (int u = 0; u < 16; u++) {
            uint4 v = row[u];
            float2 f0 = __half22float2(*(__half2*)&v.x);
            float2 f1 = __half22float2(*(__half2*)&v.y);
            float2 f2 = __half22float2(*(__half2*)&v.z);
            float2 f3 = __half22float2(*(__half2*)&v.w);
            s += (f0.x + f0.y) + (f1.x + f1.y) + (f2.x + f2.y) + (f3.x + f3.y);
        }
        g_ypart[((size_t)b*NTILE + blockIdx.x)*C_ + tid] = s;
    }

    const int r16 = lane & 15;
    const int hi8 = (lane >> 4) * 8;
    const uint32_t bX = sb + 2u*(QOFF_X + r16*SX + hi8);
    const int smm = lane >> 3, smr = lane & 7;
    const uint32_t stb = sb + 2u*(QOFF_T + ((smm>>1)*8 + smr)*ST + warp*16 + (smm&1)*8);
    const uint32_t tst0 = sb + 2u*(QOFF_T + (warp*16 + quad)*ST + qt*2);
    const uint32_t tst1 = tst0 + 2u*8*ST;

    const int o_r0 = warp*16 + quad, o_r1 = o_r0 + 8;

    #pragma unroll
    for (int which = 0; which < 3; which++) {
        const uint32_t aW = sb + 2u*(QOFF_W0 + which*C_*SW + (warp*16 + r16)*SW + hi8);

        float acc[16][4];
        #pragma unroll
        for (int nt = 0; nt < 16; nt++)
            #pragma unroll
            for (int r = 0; r < 4; r++) acc[nt][r] = 0.f;

        #pragma unroll
        for (int kc = 0; kc < 8; kc++) {
            uint32_t a0,a1,a2,a3;
            ldsm4(a0,a1,a2,a3, aW + 32u*kc);
            #pragma unroll
            for (int nt16 = 0; nt16 < 8; nt16++) {
                uint32_t b0,b1,b2,b3;
                ldsm4t(b0,b1,b2,b3, bX + 2u*(kc*16*SX + nt16*16));
                mma16(acc[2*nt16],   a0,a1,a2,a3, b0,b1);
                mma16(acc[2*nt16+1], a0,a1,a2,a3, b2,b3);
            }
        }

        const float* bias = (which == 0) ? bq : (which == 1) ? bk : bv;
        const float sc = (which == 0) ? LOG2E : 1.0f;
        float b0f = bias[o_r0], b1f = bias[o_r1];

        if (which < 2) {
            #pragma unroll
            for (int nt16 = 0; nt16 < 8; nt16++) {
                uint32_t r0 = h2u(__floats2half2_rn((acc[2*nt16][0]+b0f)*sc,   (acc[2*nt16][1]+b0f)*sc));
                uint32_t r1 = h2u(__floats2half2_rn((acc[2*nt16][2]+b1f)*sc,   (acc[2*nt16][3]+b1f)*sc));
                uint32_t r2 = h2u(__floats2half2_rn((acc[2*nt16+1][0]+b0f)*sc, (acc[2*nt16+1][1]+b0f)*sc));
                uint32_t r3 = h2u(__floats2half2_rn((acc[2*nt16+1][2]+b1f)*sc, (acc[2*nt16+1][3]+b1f)*sc));
                stsm4t(stb + 2u*(nt16*16*ST), r0, r1, r2, r3);
            }
            __syncthreads();
            __half* dsth = (which == 0) ? g_qh : g_kh;
            #pragma unroll
            for (int c2 = 0; c2 < 8; c2++) {
                int ch = tid + c2*256;
                int n = ch >> 4, ob = ch & 15;
                uint4 v = *(uint4*)&smh[QOFF_T + n*ST + ob*8];
                *(uint4*)(dsth + ((size_t)b*N_ + n0 + n)*C_ + ob*8) = v;
            }
            __syncthreads();
        } else {
            #pragma unroll
            for (int nt = 0; nt < 16; nt++) {
                sts32(tst0 + 16u*nt, h2u(__floats2half2_rn(acc[nt][0] + b0f, acc[nt][1] + b0f)));
                sts32(tst1 + 16u*nt, h2u(__floats2half2_rn(acc[nt][2] + b1f, acc[nt][3] + b1f)));
            }
            __syncthreads();
            #pragma unroll
            for (int c2 = 0; c2 < 8; c2++) {
                int ch = tid + c2*256;
                int o = ch >> 4, nb = ch & 15;
                uint4 v = *(uint4*)&smh[QOFF_T + o*ST + nb*8];
                *(uint4*)(g_vh + ((size_t)b*C_ + o)*N_ + n0 + nb*8) = v;
            }
        }
    }
}

// ---------------------------------------------------------------------------
// Flash attention: MUFU-halved softmax, P in A-fragment registers, S(t+1)
// pipelined, K double / V triple buffered, in-CTA SE MLP, coalesced epilogue.
// grid (N/64, B), block 128, 2 CTAs/SM.
// ---------------------------------------------------------------------------
__global__ void __launch_bounds__(128, 2) attn_kernel(
    const float* __restrict__ x,
    const float* __restrict__ gamma,
    const float* __restrict__ w1,
    const float* __restrict__ w2,
    float* __restrict__ out)
{
    extern __shared__ __half smh[];
    uint32_t sb = (uint32_t)__cvta_generic_to_shared(smh);
    __shared__ float ym[C_];
    __shared__ float y1_sh[8];
    __shared__ float se_sh[C_];

    const int tid  = threadIdx.x;
    const int b    = blockIdx.y;
    const int i0   = blockIdx.x * BM;
    const int warp = tid >> 5, lane = tid & 31;
    const int quad = lane >> 2, qt = lane & 3;

    const size_t bcn = (size_t)b * C_ * N_;
    const __half* qb = g_qh + (size_t)b * N_ * C_;
    const __half* kb = g_kh + (size_t)b * N_ * C_;
    const __half* vb = g_vh + (size_t)b * C_ * N_;

    // ---- prologue: G0 = (Q, K0, V0); G1 = (K1, V1) ----
    #pragma unroll
    for (int c2 = 0; c2 < 8; c2++) {
        int ch = tid + c2*128;
        int i = ch >> 4, cb = ch & 15;
        cpa16(sb + 2u*(OFF_Q + i*SQh + cb*8), qb + (size_t)(i0 + i)*C_ + cb*8);
    }
    #pragma unroll
    for (int c2 = 0; c2 < 8; c2++) {
        int ch = tid + c2*128;
        int j = ch >> 4, cb = ch & 15;
        cpa16(sb + 2u*(OFF_K + j*SKh + cb*8), kb + (size_t)j*C_ + cb*8);
    }
    #pragma unroll
    for (int c2 = 0; c2 < 8; c2++) {
        int ch = tid + c2*128;
        int c = ch >> 3, cb = ch & 7;
        cpa16(sb + 2u*(OFF_V + c*SVh + cb*8), vb + (size_t)c*N_ + cb*8);
    }
    cp_commit();
    #pragma unroll
    for (int c2 = 0; c2 < 8; c2++) {
        int ch = tid + c2*128;
        int j = ch >> 4, cb = ch & 15;
        cpa16(sb + 2u*(OFF_K + BN*SKh + j*SKh + cb*8), kb + (size_t)(BN + j)*C_ + cb*8);
    }
    #pragma unroll
    for (int c2 = 0; c2 < 8; c2++) {
        int ch = tid + c2*128;
        int c = ch >> 3, cb = ch & 7;
        cpa16(sb + 2u*(OFF_V + C_*SVh + c*SVh + cb*8), vb + (size_t)c*N_ + BN + cb*8);
    }
    cp_commit();

    // ---- SE MLP (overlapped with prologue cp.async) ----
    {
        float acc = 0.f;
        #pragma unroll
        for (int tt = 0; tt < NTILE; tt++)
            acc += g_ypart[((size_t)b*NTILE + tt)*C_ + tid];
        ym[tid] = acc * (1.f / (float)N_);
    }
    __syncthreads();
    {
        int h = tid >> 4, cl = tid & 15;
        float p = 0.f;
        #pragma unroll
        for (int u = 0; u < 8; u++) {
            int c = cl + u*16;
            p += w1[h*C_ + c] * ym[c];
        }
        #pragma unroll
        for (int off = 1; off < 16; off <<= 1)
            p += __shfl_xor_sync(0xffffffffu, p, off);
        if (cl == 0) y1_sh[h] = fmaxf(p, 0.f);
    }
    __syncthreads();
    {
        float a = 0.f;
        #pragma unroll
        for (int r = 0; r < 8; r++) a += w2[tid*8 + r] * y1_sh[r];
        se_sh[tid] = 1.f / (1.f + ex2f(-a * LOG2E));
    }

    cp_wait1();
    __syncthreads();

    float o[16][4];
    #pragma unroll
    for (int ct = 0; ct < 16; ct++)
        #pragma unroll
        for (int r = 0; r < 4; r++) o[ct][r] = 0.f;
    float m0 = -CUDART_INF_F, m1 = -CUDART_INF_F, l0 = 0.f, l1 = 0.f;

    const int r16  = lane & 15;
    const int ahi  = (lane >> 4) * 8;
    const int brow = (lane & 7) + ((lane >> 4) & 1) * 8;
    const int bcol = ((lane >> 3) & 1) * 8;

    const uint32_t aQ = sb + 2u*(OFF_Q + (warp*16 + r16)*SQh + ahi);

    // ---- S(0) ----
    float s[8][4];
    s_phase(s, aQ, sb + 2u*(OFF_K + brow*SKh + bcol));

    int vcur = 0, vnext2 = 2;
    for (int t = 0; t < 36; t++) {
        // ---- 1. softmax(t): half2 exponentials ----
        float mt0 = -CUDART_INF_F, mt1 = -CUDART_INF_F;
        #pragma unroll
        for (int nt = 0; nt < 8; nt++) {
            mt0 = fmaxf(mt0, fmaxf(s[nt][0], s[nt][1]));
            mt1 = fmaxf(mt1, fmaxf(s[nt][2], s[nt][3]));
        }
        #pragma unroll
        for (int off = 1; off < 4; off <<= 1) {
            mt0 = fmaxf(mt0, __shfl_xor_sync(0xffffffffu, mt0, off));
            mt1 = fmaxf(mt1, __shfl_xor_sync(0xffffffffu, mt1, off));
        }
        float mn0 = fmaxf(m0, mt0), mn1 = fmaxf(m1, mt1);
        float cor0 = ex2f(m0 - mn0), cor1 = ex2f(m1 - mn1);
        float rs0 = 0.f, rs1 = 0.f;
        uint32_t pa0[8], pa1[8];
        #pragma unroll
        for (int nt = 0; nt < 8; nt++) {
            pa0[nt] = ex2_h2(h2u(__floats2half2_rn(s[nt][0] - mn0, s[nt][1] - mn0)));
            pa1[nt] = ex2_h2(h2u(__floats2half2_rn(s[nt][2] - mn1, s[nt][3] - mn1)));
            float2 f0 = __half22float2(*(__half2*)&pa0[nt]);
            float2 f1 = __half22float2(*(__half2*)&pa1[nt]);
            rs0 += f0.x + f0.y;
            rs1 += f1.x + f1.y;
        }
        l0 = l0 * cor0 + rs0; m0 = mn0;
        l1 = l1 * cor1 + rs1; m1 = mn1;

        bool need = (cor0 != 1.f) | (cor1 != 1.f);
        if (__any_sync(0xffffffffu, need)) {
            #pragma unroll
            for (int ct = 0; ct < 16; ct++) {
                o[ct][0] *= cor0; o[ct][1] *= cor0;
                o[ct][2] *= cor1; o[ct][3] *= cor1;
            }
        }

        // ---- 2. K(t+1)/V(t+1) resident ----
        cp_wait0();
        __syncthreads();

        // ---- 3. stage K(t+2), V(t+2) ----
        if (t <= 33) {
            const int jn = (t + 2) * BN;
            const uint32_t kdst = sb + 2u*(OFF_K + (t & 1)*BN*SKh);
            const uint32_t vdst = sb + 2u*(OFF_V + vnext2*C_*SVh);
            #pragma unroll
            for (int c2 = 0; c2 < 8; c2++) {
                int ch = tid + c2*128;
                int j = ch >> 4, cb = ch & 15;
                cpa16(kdst + 2u*(j*SKh + cb*8), kb + (size_t)(jn + j)*C_ + cb*8);
            }
            #pragma unroll
            for (int c2 = 0; c2 < 8; c2++) {
                int ch = tid + c2*128;
                int c = ch >> 3, cb = ch & 7;
                cpa16(vdst + 2u*(c*SVh + cb*8), vb + (size_t)c*N_ + jn + cb*8);
            }
            cp_commit();
        }

        // ---- 4. S(t+1) ----
        if (t < 35)
            s_phase(s, aQ, sb + 2u*(OFF_K + ((t+1)&1)*BN*SKh + brow*SKh + bcol));

        // ---- 5. PV(t) ----
        const uint32_t vB = sb + 2u*(OFF_V + vcur*C_*SVh + brow*SVh + bcol);
        #pragma unroll
        for (int kc = 0; kc < 4; kc++) {
            uint32_t a0 = pa0[2*kc],   a1 = pa1[2*kc];
            uint32_t a2 = pa0[2*kc+1], a3 = pa1[2*kc+1];
            #pragma unroll
            for (int np = 0; np < 8; np++) {
                uint32_t b0,b1,b2,b3;
                ldsm4(b0,b1,b2,b3, vB + 2u*(np*16*SVh + kc*16));
                mma16(o[2*np],   a0,a1,a2,a3, b0,b1);
                mma16(o[2*np+1], a0,a1,a2,a3, b2,b3);
            }
        }

        vcur   = (vcur   == 2) ? 0 : vcur + 1;
        vnext2 = (vnext2 == 2) ? 0 : vnext2 + 1;
    }

    // ---- epilogue: stage O*gam/l to smem, then coalesced combine+write ----
    #pragma unroll
    for (int off = 1; off < 4; off <<= 1) {
        l0 += __shfl_xor_sync(0xffffffffu, l0, off);
        l1 += __shfl_xor_sync(0xffffffffu, l1, off);
    }
    const float gam = gamma[0];
    const float inv0 = gam / l0, inv1 = gam / l1;

    // stage: smf[i][c], stride SEP=132 (even -> float2 aligned; 33.8KB fits in
    // the dead Q/K region: < 52.2KB byte offset of live V buffers)
    float* smf = (float*)smh;
    const int li0 = warp*16 + quad, li1 = li0 + 8;
    #pragma unroll
    for (int ct = 0; ct < 16; ct++) {
        int c0 = ct*8 + qt*2;
        float2 v0 = make_float2(o[ct][0]*inv0, o[ct][1]*inv0);
        float2 v1 = make_float2(o[ct][2]*inv1, o[ct][3]*inv1);
        *(float2*)&smf[li0*SEP + c0] = v0;
        *(float2*)&smf[li1*SEP + c0] = v1;
    }
    __syncthreads();

    // coalesced pass: 16 lanes cover one c-row's 64 n-values (4 floats each)
    #pragma unroll
    for (int k2 = 0; k2 < 16; k2++) {
        int idx = tid + k2*128;            // 0..2047
        int c = idx >> 4, i4 = (idx & 15) * 4;
        float se = se_sh[c];
        size_t base = bcn + (size_t)c * N_ + i0 + i4;
        float4 xv = *(const float4*)&x[base];
        float4 ov;
        ov.x = smf[(i4+0)*SEP + c] + xv.x * se;
        ov.y = smf[(i4+1)*SEP + c] + xv.y * se;
        ov.z = smf[(i4+2)*SEP + c] + xv.z * se;
        ov.w = smf[(i4+3)*SEP + c] + xv.w * se;
        *(float4*)&out[base] = ov;
    }
}

// ---------------------------------------------------------------------------
extern "C" void kernel_launch(void* const* d_in, const int* in_sizes, int n_in,
                              void* d_out, int out_size)
{
    const float* x     = (const float*)d_in[0];
    const float* Wq    = (const float*)d_in[1];
    const float* bq    = (const float*)d_in[2];
    const float* Wk    = (const float*)d_in[3];
    const float* bk    = (const float*)d_in[4];
    const float* Wv    = (const float*)d_in[5];
    const float* bv    = (const float*)d_in[6];
    const float* se_w1 = (const float*)d_in[7];
    const float* se_w2 = (const float*)d_in[8];
    const float* gamma = (const float*)d_in[9];
    float* out = (float*)d_out;

    static int smem_set = 0;
    if (!smem_set) {
        cudaFuncSetAttribute(attn_kernel,
                             cudaFuncAttributeMaxDynamicSharedMemorySize,
                             SMEM_HALFS * (int)sizeof(__half));
        cudaFuncSetAttribute(qkv_mma_kernel,
                             cudaFuncAttributeMaxDynamicSharedMemorySize,
                             QKV_SMEM_HALFS * (int)sizeof(__half));
        smem_set = 1;
    }

    qkv_mma_kernel<<<dim3(N_/128, B_), 256, QKV_SMEM_HALFS * sizeof(__half)>>>(
        x, Wq, bq, Wk, bk, Wv, bv);
    attn_kernel<<<dim3(N_/BM, B_), 128, SMEM_HALFS * sizeof(__half)>>>(
        x, gamma, se_w1, se_w2, out);
}